// round 12
// baseline (speedup 1.0000x reference)
#include <cuda_runtime.h>

// Problem constants
#define T_STEPS 512
#define NBATCH  512
#define IN_DIM  64
#define H       100

// Layer-1 input [x(64) | h1(100) | pad(12)] -> 176 floats = 8 chunks of 22 (11 u64)
// Layer-2 input [h1(100) | h2(100) | pad(8)] -> 208 floats = 8 chunks of 26 (13 u64)
#define L1_LEN  176
#define L2_LEN  208
#define NP1     11
#define NP2     13
#define CPT1    4       // columns/thread, layer 1 (28 groups x 4 = 112 slots)
#define CPT2    3       // columns/thread, layer 2 (36 groups x 3 = 108 slots)

#define ROWS     4      // batch rows per CTA
#define NCTA     128    // 128 * 4 = 512 rows
#define NTHREADS 512    // 16 warps: warps 0-6 L1 (224 thr), warps 7-15 L2 (288 thr)
#define L2_BASE  224

typedef unsigned long long ull;

__device__ float g_W1T[H * L1_LEN];   // [col][k] transposed/concat/zero-padded
__device__ float g_W2T[H * L2_LEN];

__global__ void prep_kernel(const float* __restrict__ W1x, const float* __restrict__ W1h,
                            const float* __restrict__ W2x, const float* __restrict__ W2h) {
    int idx = blockIdx.x * blockDim.x + threadIdx.x;
    const int n1 = H * L1_LEN;
    if (idx < n1) {
        int j = idx / L1_LEN, k = idx % L1_LEN;
        float v = 0.0f;
        if (k < IN_DIM)           v = W1x[k * H + j];
        else if (k < IN_DIM + H)  v = W1h[(k - IN_DIM) * H + j];
        g_W1T[idx] = v;
    } else {
        int i2 = idx - n1;
        if (i2 < H * L2_LEN) {
            int j = i2 / L2_LEN, k = i2 % L2_LEN;
            float v = 0.0f;
            if (k < H)            v = W2x[k * H + j];
            else if (k < 2 * H)   v = W2h[(k - H) * H + j];
            g_W2T[i2] = v;
        }
    }
}

// Accurate fast tanh: 1 - 2/(exp(2x)+1).  __expf = MUFU.EX2 path, rel err ~1e-6.
__device__ __forceinline__ float fast_tanh(float x) {
    float e = __expf(2.0f * x);
    return 1.0f - __fdividef(2.0f, e + 1.0f);
}

// Packed fp32 FMA (sm_103a FFMA2): acc = a*b + acc, two k-lanes at once.
__device__ __forceinline__ void ffma2(ull& acc, ull a, ull b) {
    asm("fma.rn.f32x2 %0, %1, %2, %0;" : "+l"(acc) : "l"(a), "l"(b));
}

__device__ __forceinline__ float hadd2(ull a) {
    float lo, hi;
    asm("mov.b64 {%0, %1}, %2;" : "=f"(lo), "=f"(hi) : "l"(a));
    return lo + hi;
}

// Reduce-scatter 8 values over the 8 k-split lanes of a group.
// Lane s (=lane&7) ends with the full sum of value index s.
__device__ __forceinline__ float reduce8(const float (&v)[8], int s) {
    const bool h4 = (s & 4) != 0, h2 = (s & 2) != 0, h1 = (s & 1) != 0;
    float a[4], b[2];
    #pragma unroll
    for (int k = 0; k < 4; ++k) {
        float keep = h4 ? v[k + 4] : v[k];
        float send = h4 ? v[k] : v[k + 4];
        a[k] = keep + __shfl_xor_sync(0xffffffffu, send, 4);
    }
    #pragma unroll
    for (int k = 0; k < 2; ++k) {
        float keep = h2 ? a[k + 2] : a[k];
        float send = h2 ? a[k] : a[k + 2];
        b[k] = keep + __shfl_xor_sync(0xffffffffu, send, 2);
    }
    float keep = h1 ? b[1] : b[0];
    float send = h1 ? b[0] : b[1];
    return keep + __shfl_xor_sync(0xffffffffu, send, 1);
}

__global__ void __launch_bounds__(NTHREADS, 1)
rnn_kernel(const float* __restrict__ x,
           const float* __restrict__ b1, const float* __restrict__ b2,
           const float* __restrict__ Wo, const float* __restrict__ bo,
           float* __restrict__ out) {
    __shared__ __align__(16) float s_in1[2][ROWS][L1_LEN];
    __shared__ __align__(16) float s_in2[2][ROWS][L2_LEN];

    const int t  = threadIdx.x;
    const int b0 = blockIdx.x * ROWS;
    const float4* __restrict__ xg4 = (const float4*)x;

    for (int i = t; i < 2 * ROWS * L1_LEN; i += NTHREADS) ((float*)s_in1)[i] = 0.0f;
    for (int i = t; i < 2 * ROWS * L2_LEN; i += NTHREADS) ((float*)s_in2)[i] = 0.0f;
    __syncthreads();

    // Stage x(0) into buffer 0 (done by L2-side threads u<64; any threads work here).
    if (t >= L2_BASE && t < L2_BASE + 64) {
        int u = t - L2_BASE;
        int pr = (u >> 4) & 3, pd = u & 15;
        ((float4*)&s_in1[0][pr][0])[pd] =
            xg4[(b0 + pr) * (T_STEPS * (IN_DIM / 4)) + pd];
    }
    __syncthreads();

    // Warp-specialized phase loops. Each path executes exactly one __syncthreads
    // per phase (513 each) so barrier arrival counts always match.
    if (t < L2_BASE) {
        // ---------------- Layer 1: 7 warps, 28 groups, CPT=4 ----------------
        const int g = t >> 3, s = t & 7;
        ull w[CPT1][NP1];
        #pragma unroll
        for (int c = 0; c < CPT1; ++c) {
            int col = CPT1 * g + c; if (col >= H) col = H - 1;
            const ull* p = (const ull*)(g_W1T + col * L1_LEN) + s * NP1;
            #pragma unroll
            for (int i = 0; i < NP1; ++i) w[c][i] = p[i];
        }
        const int  ocol   = CPT1 * g + (s >> 1);
        const bool ostore = (ocol < H);
        const float biasv = b1[ostore ? ocol : 0];
        const int  orp    = s & 1;

        for (int p = 0; p <= T_STEPS; ++p) {
            const int pb = p & 1;
            if (p < T_STEPS) {
                #pragma unroll
                for (int rb = 0; rb < ROWS; rb += 2) {
                    float v8[8];
                    #pragma unroll
                    for (int r2 = 0; r2 < 2; ++r2) {
                        const ull* in = (const ull*)&s_in1[pb][rb + r2][0] + s * NP1;
                        ull acc[CPT1];
                        #pragma unroll
                        for (int c = 0; c < CPT1; ++c) acc[c] = 0ull;
                        #pragma unroll
                        for (int i = 0; i < NP1; ++i) {
                            ull vv = in[i];
                            #pragma unroll
                            for (int c = 0; c < CPT1; ++c) ffma2(acc[c], w[c][i], vv);
                        }
                        #pragma unroll
                        for (int c = 0; c < CPT1; ++c) v8[c * 2 + r2] = hadd2(acc[c]);
                    }
                    float red = reduce8(v8, s);
                    float h = fast_tanh(red + biasv);
                    if (ostore) {
                        int r = rb + orp;
                        s_in1[pb ^ 1][r][IN_DIM + ocol] = h;   // next L1's h1(t-1)
                        s_in2[pb ^ 1][r][ocol]          = h;   // next L2's h1(t-1)
                        if (p == T_STEPS - 1)
                            out[NBATCH + (b0 + r) * H + ocol] = h;   // h1_T
                    }
                }
            }
            __syncthreads();
        }
    } else {
        // ---------------- Layer 2: 9 warps, 36 groups, CPT=3 ----------------
        const int u = t - L2_BASE;
        const int g = u >> 3, s = u & 7;
        ull w[CPT2][NP2];
        #pragma unroll
        for (int c = 0; c < CPT2; ++c) {
            int col = CPT2 * g + c; if (col >= H) col = H - 1;
            const ull* p = (const ull*)(g_W2T + col * L2_LEN) + s * NP2;
            #pragma unroll
            for (int i = 0; i < NP2; ++i) w[c][i] = p[i];
        }
        const int  ocol   = CPT2 * g + (s >> 1);
        const bool ostore = (s < 2 * CPT2) && (ocol < H);
        const float biasv = b2[ostore ? ocol : 0];
        const int  orp    = s & 1;

        // x-prefetch lives on L2 warps (they are idle at p=0 compute anyway).
        const bool isPre = (u < 64);
        const int  pre_r = (u >> 4) & 3, pre_d = u & 15;

        for (int p = 0; p <= T_STEPS; ++p) {
            const int pb = p & 1;
            float4 xpre;
            const bool doPre = isPre && (p + 1 < T_STEPS);
            if (doPre)
                xpre = xg4[(b0 + pre_r) * (T_STEPS * (IN_DIM / 4)) + (p + 1) * (IN_DIM / 4) + pre_d];

            if (p >= 1) {
                #pragma unroll
                for (int rb = 0; rb < ROWS; rb += 2) {
                    float v8[8];
                    v8[6] = 0.0f; v8[7] = 0.0f;
                    #pragma unroll
                    for (int r2 = 0; r2 < 2; ++r2) {
                        const ull* in = (const ull*)&s_in2[pb][rb + r2][0] + s * NP2;
                        ull acc[CPT2];
                        #pragma unroll
                        for (int c = 0; c < CPT2; ++c) acc[c] = 0ull;
                        #pragma unroll
                        for (int i = 0; i < NP2; ++i) {
                            ull vv = in[i];
                            #pragma unroll
                            for (int c = 0; c < CPT2; ++c) ffma2(acc[c], w[c][i], vv);
                        }
                        #pragma unroll
                        for (int c = 0; c < CPT2; ++c) v8[c * 2 + r2] = hadd2(acc[c]);
                    }
                    float red = reduce8(v8, s);
                    float h = fast_tanh(red + biasv);
                    if (ostore) {
                        int r = rb + orp;
                        s_in2[pb ^ 1][r][H + ocol] = h;        // next L2's h2(t-1)
                        if (p == T_STEPS)
                            out[NBATCH + NBATCH * H + (b0 + r) * H + ocol] = h;   // h2_T
                    }
                }
            }

            if (doPre)
                ((float4*)&s_in1[pb ^ 1][pre_r][0])[pre_d] = xpre;

            __syncthreads();
        }
    }

    // out = h2_T @ Wo + bo.  h2(T-1) was written at phase 512 into buffer 1.
    if (t < ROWS) {
        float acc = bo[0];
        #pragma unroll 4
        for (int k = 0; k < H; ++k)
            acc = fmaf(s_in2[1][t][H + k], Wo[k], acc);
        out[b0 + t] = acc;
    }
}

extern "C" void kernel_launch(void* const* d_in, const int* in_sizes, int n_in,
                              void* d_out, int out_size) {
    const float* x   = (const float*)d_in[0];
    const float* W1x = (const float*)d_in[1];
    const float* W1h = (const float*)d_in[2];
    const float* b1  = (const float*)d_in[3];
    const float* W2x = (const float*)d_in[4];
    const float* W2h = (const float*)d_in[5];
    const float* b2  = (const float*)d_in[6];
    const float* Wo  = (const float*)d_in[7];
    const float* bo  = (const float*)d_in[8];
    float* out = (float*)d_out;

    // Build transposed/padded weight images (38400 elements total).
    prep_kernel<<<150, 256>>>(W1x, W1h, W2x, W2h);

    // Persistent batch-partitioned RNN: 128 CTAs x 4 rows, no inter-CTA sync.
    rnn_kernel<<<NCTA, NTHREADS>>>(x, b1, b2, Wo, bo, out);
}